// round 1
// baseline (speedup 1.0000x reference)
#include <cuda_runtime.h>

// Problem constants (fixed by the dataset)
#define BB 32
#define LL 1024
#define HH 384
#define H4 (HH / 4)          // 96 float4 per row
#define ROWS_PER_BLOCK 4     // 4 rows * 96 lanes = 384 threads

// Scratch (no cudaMalloc allowed)
__device__ int g_cum[BB * LL];
__device__ int g_total[BB];

// ---------------------------------------------------------------------------
// Kernel 1: per-batch inclusive scan of durations (one block of 1024 threads
// per batch; warp shfl scan + cross-warp scan).
// ---------------------------------------------------------------------------
__global__ void lr_scan_kernel(const int* __restrict__ dur) {
    const int b = blockIdx.x;
    const int tid = threadIdx.x;            // 0..1023
    const int lane = tid & 31;
    const int wid = tid >> 5;

    int x = dur[b * LL + tid];

    // warp inclusive scan
    #pragma unroll
    for (int o = 1; o < 32; o <<= 1) {
        int y = __shfl_up_sync(0xFFFFFFFFu, x, o);
        if (lane >= o) x += y;
    }

    __shared__ int wsum[32];
    if (lane == 31) wsum[wid] = x;
    __syncthreads();

    if (wid == 0) {
        int s = wsum[lane];
        #pragma unroll
        for (int o = 1; o < 32; o <<= 1) {
            int y = __shfl_up_sync(0xFFFFFFFFu, s, o);
            if (lane >= o) s += y;
        }
        wsum[lane] = s;
    }
    __syncthreads();

    if (wid > 0) x += wsum[wid - 1];

    g_cum[b * LL + tid] = x;
    if (tid == LL - 1) g_total[b] = x;
}

// ---------------------------------------------------------------------------
// Kernel 2: expand. One row (b, t) per 96-lane group; float4 copy of the
// selected source row (searchsorted-right on the inclusive cumsum), zeros +
// mask=0 beyond total[b].
// ---------------------------------------------------------------------------
__global__ void lr_expand_kernel(const float* __restrict__ hid,
                                 float* __restrict__ out,
                                 float* __restrict__ mask,
                                 int T, long long n_rows) {
    const int tid = threadIdx.x;            // 0..383
    const int row_in_block = tid / H4;      // 0..3
    const int lane = tid - row_in_block * H4;

    const long long row = (long long)blockIdx.x * ROWS_PER_BLOCK + row_in_block;
    if (row >= n_rows) return;

    const int b = (int)(row / T);
    const int t = (int)(row - (long long)b * T);

    float4* dst = (float4*)(out + row * HH);

    const int total = g_total[b];
    if (t < total) {
        // searchsorted right: first i with cum[i] > t
        const int* __restrict__ cum = g_cum + b * LL;
        int lo = 0, hi = LL;
        #pragma unroll 10
        while (lo < hi) {
            int mid = (lo + hi) >> 1;
            if (cum[mid] <= t) lo = mid + 1; else hi = mid;
        }
        int idx = lo < LL - 1 ? lo : LL - 1;

        const float4* __restrict__ src =
            (const float4*)(hid + ((long long)b * LL + idx) * HH);
        dst[lane] = src[lane];
        if (lane == 0) mask[row] = 1.0f;
    } else {
        dst[lane] = make_float4(0.f, 0.f, 0.f, 0.f);
        if (lane == 0) mask[row] = 0.0f;
    }
}

// ---------------------------------------------------------------------------
extern "C" void kernel_launch(void* const* d_in, const int* in_sizes, int n_in,
                              void* d_out, int out_size) {
    const float* hid = (const float*)d_in[0];   // (B, L, H) f32
    const int*   dur = (const int*)d_in[1];     // (B, L) i32

    // out_size = B*T*H + B*T = B*T*(H+1)
    const int T = out_size / (BB * (HH + 1));
    const long long n_rows = (long long)BB * T;

    float* out  = (float*)d_out;                // B*T*H
    float* mask = (float*)d_out + n_rows * HH;  // B*T

    lr_scan_kernel<<<BB, LL>>>(dur);

    const int n_blocks = (int)((n_rows + ROWS_PER_BLOCK - 1) / ROWS_PER_BLOCK);
    lr_expand_kernel<<<n_blocks, ROWS_PER_BLOCK * H4>>>(hid, out, mask, T, n_rows);
}

// round 2
// speedup vs baseline: 1.7071x; 1.7071x over previous
#include <cuda_runtime.h>

// Problem constants (fixed by the dataset)
#define BB 32
#define LL 1024
#define HH 384
#define H4 (HH / 4)          // 96 float4 per row
#define ROWS_PER_BLOCK 4
#define MAX_DUR 8
#define T_MAX (LL * (MAX_DUR - 1))   // 7168

// Scratch (no cudaMalloc allowed)
__device__ int g_idx[BB * T_MAX];    // source index per output frame
__device__ int g_total[BB];

// ---------------------------------------------------------------------------
// Kernel 1: per-batch inclusive scan of durations + direct scatter of the
// source index into g_idx[b*T + t] for t in [cum-dur, cum). No cum array,
// no searchsorted needed afterwards.
// ---------------------------------------------------------------------------
__global__ void lr_scan_scatter_kernel(const int* __restrict__ dur, int T) {
    const int b = blockIdx.x;
    const int tid = threadIdx.x;            // 0..1023
    const int lane = tid & 31;
    const int wid = tid >> 5;

    const int d = dur[b * LL + tid];
    int x = d;

    // warp inclusive scan
    #pragma unroll
    for (int o = 1; o < 32; o <<= 1) {
        int y = __shfl_up_sync(0xFFFFFFFFu, x, o);
        if (lane >= o) x += y;
    }

    __shared__ int wsum[32];
    if (lane == 31) wsum[wid] = x;
    __syncthreads();

    if (wid == 0) {
        int s = wsum[lane];
        #pragma unroll
        for (int o = 1; o < 32; o <<= 1) {
            int y = __shfl_up_sync(0xFFFFFFFFu, s, o);
            if (lane >= o) s += y;
        }
        wsum[lane] = s;
    }
    __syncthreads();

    if (wid > 0) x += wsum[wid - 1];        // inclusive cumsum at position tid

    // scatter: output frames [x-d, x) come from source row tid
    int* __restrict__ idx_row = g_idx + b * T;
    const int start = x - d;
    #pragma unroll
    for (int k = 0; k < MAX_DUR; k++) {
        if (k < d) idx_row[start + k] = tid;
    }

    if (tid == LL - 1) g_total[b] = x;
}

// ---------------------------------------------------------------------------
// Kernel 2: expand. 2D block (96 lanes, 4 rows). One float4 per thread,
// source row comes from precomputed g_idx (L1 broadcast load).
// ---------------------------------------------------------------------------
__global__ void lr_expand_kernel(const float* __restrict__ hid,
                                 float* __restrict__ out,
                                 float* __restrict__ mask,
                                 int T, long long n_rows) {
    const int lane = threadIdx.x;           // 0..95
    const long long row = (long long)blockIdx.x * ROWS_PER_BLOCK + threadIdx.y;
    if (row >= n_rows) return;

    const int b = (int)(row / T);
    const int t = (int)(row - (long long)b * T);

    float4* dst = (float4*)(out + row * HH);

    if (t < g_total[b]) {
        const int idx = g_idx[b * T + t];
        const float4* __restrict__ src =
            (const float4*)(hid + ((long long)b * LL + idx) * HH);
        dst[lane] = src[lane];
        if (lane == 0) mask[row] = 1.0f;
    } else {
        dst[lane] = make_float4(0.f, 0.f, 0.f, 0.f);
        if (lane == 0) mask[row] = 0.0f;
    }
}

// ---------------------------------------------------------------------------
extern "C" void kernel_launch(void* const* d_in, const int* in_sizes, int n_in,
                              void* d_out, int out_size) {
    const float* hid = (const float*)d_in[0];   // (B, L, H) f32
    const int*   dur = (const int*)d_in[1];     // (B, L) i32

    // out_size = B*T*H + B*T = B*T*(H+1)
    const int T = out_size / (BB * (HH + 1));
    const long long n_rows = (long long)BB * T;

    float* out  = (float*)d_out;                // B*T*H
    float* mask = (float*)d_out + n_rows * HH;  // B*T

    lr_scan_scatter_kernel<<<BB, LL>>>(dur, T);

    const int n_blocks = (int)((n_rows + ROWS_PER_BLOCK - 1) / ROWS_PER_BLOCK);
    dim3 blk(H4, ROWS_PER_BLOCK);
    lr_expand_kernel<<<n_blocks, blk>>>(hid, out, mask, T, n_rows);
}

// round 3
// speedup vs baseline: 2.5499x; 1.4937x over previous
#include <cuda_runtime.h>

// Problem constants (fixed by the dataset)
#define BB 32
#define LL 1024
#define HH 384
#define H4 (HH / 4)          // 96 float4 per row
#define MAX_DUR 8
#define T_MAX (LL * (MAX_DUR - 1))   // 7168

// Scratch (no cudaMalloc allowed)
__device__ int g_idx[BB * T_MAX];    // source index per output frame
__device__ int g_total[BB];

// ---------------------------------------------------------------------------
// Kernel 1: per-batch inclusive scan of durations + direct scatter of the
// source index into g_idx[b*T + t] for t in [cum-dur, cum).
// ---------------------------------------------------------------------------
__global__ void lr_scan_scatter_kernel(const int* __restrict__ dur, int T) {
    const int b = blockIdx.x;
    const int tid = threadIdx.x;            // 0..1023
    const int lane = tid & 31;
    const int wid = tid >> 5;

    const int d = dur[b * LL + tid];
    int x = d;

    #pragma unroll
    for (int o = 1; o < 32; o <<= 1) {
        int y = __shfl_up_sync(0xFFFFFFFFu, x, o);
        if (lane >= o) x += y;
    }

    __shared__ int wsum[32];
    if (lane == 31) wsum[wid] = x;
    __syncthreads();

    if (wid == 0) {
        int s = wsum[lane];
        #pragma unroll
        for (int o = 1; o < 32; o <<= 1) {
            int y = __shfl_up_sync(0xFFFFFFFFu, s, o);
            if (lane >= o) s += y;
        }
        wsum[lane] = s;
    }
    __syncthreads();

    if (wid > 0) x += wsum[wid - 1];        // inclusive cumsum at position tid

    int* __restrict__ idx_row = g_idx + b * T;
    const int start = x - d;
    #pragma unroll
    for (int k = 0; k < MAX_DUR; k++) {
        if (k < d) idx_row[start + k] = tid;
    }

    if (tid == LL - 1) g_total[b] = x;
}

// ---------------------------------------------------------------------------
// Kernel 2: expand, 2 rows per thread for ILP. Grid (ceil(T/8), B),
// block (96, 4): thread (lane, y) handles t = t_base+y and t_base+y+4.
// Streaming stores keep the gathered input resident in L2.
// ---------------------------------------------------------------------------
__global__ void lr_expand_kernel(const float* __restrict__ hid,
                                 float* __restrict__ out,
                                 float* __restrict__ mask,
                                 int T) {
    const int lane = threadIdx.x;           // 0..95
    const int b = blockIdx.y;
    const int t0 = blockIdx.x * 8 + threadIdx.y;      // rows t0 and t0+4
    const int t1 = t0 + 4;
    const int total = g_total[b];

    const int* __restrict__ idx_row = g_idx + b * T;
    const float4* __restrict__ src_base = (const float4*)(hid) + (long long)b * LL * H4;

    // independent idx loads first (both in flight)
    const bool a0 = (t0 < T) && (t0 < total);
    const bool a1 = (t1 < T) && (t1 < total);
    int i0 = a0 ? idx_row[t0] : 0;
    int i1 = a1 ? idx_row[t1] : 0;

    float4 v0 = make_float4(0.f, 0.f, 0.f, 0.f);
    float4 v1 = v0;
    if (a0) v0 = src_base[(long long)i0 * H4 + lane];
    if (a1) v1 = src_base[(long long)i1 * H4 + lane];

    float4* __restrict__ dst0 = (float4*)(out) + ((long long)b * T + t0) * H4;
    float4* __restrict__ dst1 = dst0 + 4LL * H4;

    if (t0 < T) {
        __stcs(dst0 + lane, v0);
        if (lane == 0) mask[(long long)b * T + t0] = a0 ? 1.0f : 0.0f;
    }
    if (t1 < T) {
        __stcs(dst1 + lane, v1);
        if (lane == 0) mask[(long long)b * T + t1] = a1 ? 1.0f : 0.0f;
    }
}

// ---------------------------------------------------------------------------
extern "C" void kernel_launch(void* const* d_in, const int* in_sizes, int n_in,
                              void* d_out, int out_size) {
    const float* hid = (const float*)d_in[0];   // (B, L, H) f32
    const int*   dur = (const int*)d_in[1];     // (B, L) i32

    // out_size = B*T*H + B*T = B*T*(H+1)
    const int T = out_size / (BB * (HH + 1));
    const long long n_rows = (long long)BB * T;

    float* out  = (float*)d_out;                // B*T*H
    float* mask = (float*)d_out + n_rows * HH;  // B*T

    lr_scan_scatter_kernel<<<BB, LL>>>(dur, T);

    dim3 grid((T + 7) / 8, BB);
    dim3 blk(H4, 4);
    lr_expand_kernel<<<grid, blk>>>(hid, out, mask, T);
}

// round 5
// speedup vs baseline: 2.8039x; 1.0996x over previous
#include <cuda_runtime.h>

// Problem constants (fixed by the dataset)
#define BB 32
#define LL 1024
#define HH 384
#define H4 (HH / 4)          // 96 float4 per row
#define MAX_DUR 8
#define T_MAX (LL * (MAX_DUR - 1))   // 7168

// Scratch (no cudaMalloc allowed)
__device__ __align__(16) int g_idx[BB * T_MAX];  // source index per output frame
__device__ int g_total[BB];

// ---------------------------------------------------------------------------
// Kernel 1: per-batch inclusive scan of durations + direct scatter of the
// source index into g_idx[b*T + t] for t in [cum-dur, cum).
// ---------------------------------------------------------------------------
__global__ void lr_scan_scatter_kernel(const int* __restrict__ dur, int T) {
    const int b = blockIdx.x;
    const int tid = threadIdx.x;            // 0..1023
    const int lane = tid & 31;
    const int wid = tid >> 5;

    const int d = dur[b * LL + tid];
    int x = d;

    #pragma unroll
    for (int o = 1; o < 32; o <<= 1) {
        int y = __shfl_up_sync(0xFFFFFFFFu, x, o);
        if (lane >= o) x += y;
    }

    __shared__ int wsum[32];
    if (lane == 31) wsum[wid] = x;
    __syncthreads();

    if (wid == 0) {
        int s = wsum[lane];
        #pragma unroll
        for (int o = 1; o < 32; o <<= 1) {
            int y = __shfl_up_sync(0xFFFFFFFFu, s, o);
            if (lane >= o) s += y;
        }
        wsum[lane] = s;
    }
    __syncthreads();

    if (wid > 0) x += wsum[wid - 1];        // inclusive cumsum at position tid

    int* __restrict__ idx_row = g_idx + b * T;
    const int start = x - d;
    #pragma unroll
    for (int k = 0; k < MAX_DUR; k++) {
        if (k < d) idx_row[start + k] = tid;
    }

    if (tid == LL - 1) g_total[b] = x;
}

// ---------------------------------------------------------------------------
// Kernel 2: expand, 4 contiguous rows per thread (MLP=4, int4 idx load).
// Grid (ceil(T/16), B), block (96, 4): thread (lane, y) handles rows
// t_base + 4y + {0..3}. Streaming stores keep gathered input in L2.
// ---------------------------------------------------------------------------
__global__ void lr_expand_kernel(const float* __restrict__ hid,
                                 float* __restrict__ out,
                                 float* __restrict__ mask,
                                 int T) {
    const int lane = threadIdx.x;           // 0..95
    const int b = blockIdx.y;
    const int t0 = blockIdx.x * 16 + threadIdx.y * 4;  // rows t0..t0+3
    const int total = g_total[b];

    if (t0 >= T) return;

    // one vector load of 4 source indices (g_idx base and T*4 both 16B-aligned
    // only if T%4==0; fall back to scalar when unaligned)
    int i0 = 0, i1 = 0, i2 = 0, i3 = 0;
    const int* __restrict__ idx_row = g_idx + b * T;
    if (((b * T + t0) & 3) == 0 && t0 + 3 < T) {
        int4 iv = *(const int4*)(idx_row + t0);
        i0 = iv.x; i1 = iv.y; i2 = iv.z; i3 = iv.w;
    } else {
        i0 = idx_row[t0];
        if (t0 + 1 < T) i1 = idx_row[t0 + 1];
        if (t0 + 2 < T) i2 = idx_row[t0 + 2];
        if (t0 + 3 < T) i3 = idx_row[t0 + 3];
    }

    const bool a0 = (t0     < total);
    const bool a1 = (t0 + 1 < total) && (t0 + 1 < T);
    const bool a2 = (t0 + 2 < total) && (t0 + 2 < T);
    const bool a3 = (t0 + 3 < total) && (t0 + 3 < T);

    const float4* __restrict__ src = (const float4*)(hid) + (long long)b * LL * H4 + lane;
    float4 z = make_float4(0.f, 0.f, 0.f, 0.f);
    float4 v0 = z, v1 = z, v2 = z, v3 = z;
    if (a0) v0 = src[(long long)i0 * H4];
    if (a1) v1 = src[(long long)i1 * H4];
    if (a2) v2 = src[(long long)i2 * H4];
    if (a3) v3 = src[(long long)i3 * H4];

    float4* __restrict__ dst = (float4*)(out) + ((long long)b * T + t0) * H4 + lane;
    __stcs(dst, v0);
    if (t0 + 1 < T) __stcs(dst +     H4, v1);
    if (t0 + 2 < T) __stcs(dst + 2 * H4, v2);
    if (t0 + 3 < T) __stcs(dst + 3 * H4, v3);

    if (lane == 0) {
        float* __restrict__ m = mask + (long long)b * T + t0;
        m[0] = a0 ? 1.0f : 0.0f;
        if (t0 + 1 < T) m[1] = a1 ? 1.0f : 0.0f;
        if (t0 + 2 < T) m[2] = a2 ? 1.0f : 0.0f;
        if (t0 + 3 < T) m[3] = a3 ? 1.0f : 0.0f;
    }
}

// ---------------------------------------------------------------------------
extern "C" void kernel_launch(void* const* d_in, const int* in_sizes, int n_in,
                              void* d_out, int out_size) {
    const float* hid = (const float*)d_in[0];   // (B, L, H) f32
    const int*   dur = (const int*)d_in[1];     // (B, L) i32

    // out_size = B*T*H + B*T = B*T*(H+1)
    const int T = out_size / (BB * (HH + 1));
    const long long n_rows = (long long)BB * T;

    float* out  = (float*)d_out;                // B*T*H
    float* mask = (float*)d_out + n_rows * HH;  // B*T

    lr_scan_scatter_kernel<<<BB, LL>>>(dur, T);

    dim3 grid((T + 15) / 16, BB);
    dim3 blk(H4, 4);
    lr_expand_kernel<<<grid, blk>>>(hid, out, mask, T);
}

// round 6
// speedup vs baseline: 2.8279x; 1.0086x over previous
#include <cuda_runtime.h>

// Problem constants (fixed by the dataset)
#define BB 32
#define LL 1024
#define HH 384
#define H4 (HH / 4)          // 96 float4 per row
#define MAX_DUR 8
#define T_MAX (LL * (MAX_DUR - 1))   // 7168, multiple of 4 -> int4-aligned rows
#define RPT 8                // rows per thread
#define TILE_T 32            // rows per block (4 y-slices * 8)

// Scratch (no cudaMalloc allowed). Row stride is T_MAX so every int4 idx
// load is aligned regardless of runtime T. Unwritten entries stay 0 (safe).
__device__ __align__(16) int g_idx[BB * T_MAX];
__device__ int g_total[BB];

// ---------------------------------------------------------------------------
// Kernel 1: per-batch inclusive scan of durations + scatter of source index
// into g_idx[b*T_MAX + t] for t in [cum-dur, cum).
// ---------------------------------------------------------------------------
__global__ void lr_scan_scatter_kernel(const int* __restrict__ dur) {
    const int b = blockIdx.x;
    const int tid = threadIdx.x;            // 0..1023
    const int lane = tid & 31;
    const int wid = tid >> 5;

    const int d = dur[b * LL + tid];
    int x = d;

    #pragma unroll
    for (int o = 1; o < 32; o <<= 1) {
        int y = __shfl_up_sync(0xFFFFFFFFu, x, o);
        if (lane >= o) x += y;
    }

    __shared__ int wsum[32];
    if (lane == 31) wsum[wid] = x;
    __syncthreads();

    if (wid == 0) {
        int s = wsum[lane];
        #pragma unroll
        for (int o = 1; o < 32; o <<= 1) {
            int y = __shfl_up_sync(0xFFFFFFFFu, s, o);
            if (lane >= o) s += y;
        }
        wsum[lane] = s;
    }
    __syncthreads();

    if (wid > 0) x += wsum[wid - 1];        // inclusive cumsum at position tid

    int* __restrict__ idx_row = g_idx + b * T_MAX;
    const int start = x - d;
    #pragma unroll
    for (int k = 0; k < MAX_DUR; k++) {
        if (k < d) idx_row[start + k] = tid;
    }

    if (tid == LL - 1) g_total[b] = x;
}

// ---------------------------------------------------------------------------
// Kernel 2: expand, 8 contiguous rows per thread. Block (96,4) = 384 thr,
// each block covers 32 output rows of one batch. All 8 gathers issued before
// any store (front-batched MLP=8); output via streaming stores.
// ---------------------------------------------------------------------------
__global__ void __launch_bounds__(384, 3)
lr_expand_kernel(const float* __restrict__ hid,
                 float* __restrict__ out,
                 float* __restrict__ mask,
                 int T) {
    const int lane = threadIdx.x;           // 0..95
    const int b = blockIdx.y;
    const int t0 = blockIdx.x * TILE_T + threadIdx.y * RPT;
    if (t0 >= T) return;

    const int total = g_total[b];

    // idx loads: always in-bounds and 16B-aligned (stride T_MAX, t0 % 8 == 0)
    const int* __restrict__ idx_row = g_idx + b * T_MAX;
    int idx[RPT];
    *(int4*)(&idx[0]) = *(const int4*)(idx_row + t0);
    *(int4*)(&idx[4]) = *(const int4*)(idx_row + t0 + 4);

    const float4* __restrict__ src =
        (const float4*)(hid) + (long long)b * LL * H4 + lane;
    const float4 z = make_float4(0.f, 0.f, 0.f, 0.f);

    float4 v[RPT];
    #pragma unroll
    for (int k = 0; k < RPT; k++) {
        float4 vv = z;
        if (t0 + k < total) vv = src[idx[k] * H4];
        v[k] = vv;
    }

    float4* __restrict__ dst =
        (float4*)(out) + ((long long)b * T + t0) * H4 + lane;

    if (t0 + RPT <= T) {
        #pragma unroll
        for (int k = 0; k < RPT; k++) __stcs(dst + k * H4, v[k]);

        if (lane == 0) {
            float4 m0, m1;
            m0.x = (t0 + 0 < total) ? 1.f : 0.f;
            m0.y = (t0 + 1 < total) ? 1.f : 0.f;
            m0.z = (t0 + 2 < total) ? 1.f : 0.f;
            m0.w = (t0 + 3 < total) ? 1.f : 0.f;
            m1.x = (t0 + 4 < total) ? 1.f : 0.f;
            m1.y = (t0 + 5 < total) ? 1.f : 0.f;
            m1.z = (t0 + 6 < total) ? 1.f : 0.f;
            m1.w = (t0 + 7 < total) ? 1.f : 0.f;
            float4* mp = (float4*)(mask + (long long)b * T + t0);
            __stcs(mp, m0);
            __stcs(mp + 1, m1);
        }
    } else {
        // T-tail: per-row bounds
        #pragma unroll
        for (int k = 0; k < RPT; k++) {
            if (t0 + k < T) {
                __stcs(dst + k * H4, v[k]);
                if (lane == 0)
                    mask[(long long)b * T + t0 + k] = (t0 + k < total) ? 1.f : 0.f;
            }
        }
    }
}

// ---------------------------------------------------------------------------
extern "C" void kernel_launch(void* const* d_in, const int* in_sizes, int n_in,
                              void* d_out, int out_size) {
    const float* hid = (const float*)d_in[0];   // (B, L, H) f32
    const int*   dur = (const int*)d_in[1];     // (B, L) i32

    // out_size = B*T*H + B*T = B*T*(H+1)
    const int T = out_size / (BB * (HH + 1));
    const long long n_rows = (long long)BB * T;

    float* out  = (float*)d_out;                // B*T*H
    float* mask = (float*)d_out + n_rows * HH;  // B*T

    lr_scan_scatter_kernel<<<BB, LL>>>(dur);

    dim3 grid((T + TILE_T - 1) / TILE_T, BB);
    dim3 blk(H4, 4);
    lr_expand_kernel<<<grid, blk>>>(hid, out, mask, T);
}